// round 3
// baseline (speedup 1.0000x reference)
#include <cuda_runtime.h>

// Problem constants (fixed shapes from reference_code)
#define BB    64
#define WW    300
#define SS    512
#define DD    768
#define LMAXV 4
#define VPT   6          // float4 chunks per lane: (768/4)/32

__device__ int g_first[BB];
__device__ int g_fill[BB];

// Pass 1: per-batch first break index and fill word id (tiny: 64 warps)
__global__ void find_first_kernel(const int* __restrict__ word_index) {
    int b = blockIdx.x;
    int lane = threadIdx.x;
    int best = WW;
    for (int w = lane; w < WW; w += 32) {
        const int* wi = word_index + (b * WW + w) * 3;
        int st = wi[1], en = wi[2];
        if (en < SS && (en - st) <= 0) best = min(best, w);
    }
    #pragma unroll
    for (int o = 16; o; o >>= 1) best = min(best, __shfl_xor_sync(0xffffffffu, best, o));
    if (lane == 0) {
        g_first[b] = best;
        int fw = min(best, WW - 1);
        g_fill[b] = word_index[(b * WW + fw) * 3];
    }
}

// Pass 2: one warp per (b,w) word, branch-free 4-row interleaved loads
__global__ __launch_bounds__(256, 4) void weighted_embed_kernel(
    const float* __restrict__ ernie,
    const float* __restrict__ emb,
    const int*   __restrict__ word_index,
    float*       __restrict__ out)
{
    int gw = blockIdx.x * 8 + (threadIdx.x >> 5);
    if (gw >= BB * WW) return;
    int lane = threadIdx.x & 31;
    int b = gw / WW, w = gw - b * WW;

    float4* orow = (float4*)(out + (size_t)gw * DD);

    // Fill path: w >= first  ->  out = word_embedding[fill_id]
    if (w >= g_first[b]) {
        const float4* frow = (const float4*)(emb + (size_t)g_fill[b] * DD);
        #pragma unroll
        for (int k = 0; k < VPT; k++) __stcs(&orow[k * 32 + lane], frow[k * 32 + lane]);
        return;
    }

    const int* wi = word_index + gw * 3;
    int wid = wi[0], st = wi[1], en = wi[2];

    // we = word_embedding[wid], kept in registers (rows mostly read-once -> ldcs)
    const float4* werow = (const float4*)(emb + (size_t)wid * DD);
    float4 we[VPT];
    #pragma unroll
    for (int k = 0; k < VPT; k++) we[k] = __ldcs(&werow[k * 32 + lane]);

    // Out-of-range path: out = we
    if (en >= SS) {
        #pragma unroll
        for (int k = 0; k < VPT; k++) __stcs(&orow[k * 32 + lane], we[k]);
        return;
    }

    int span  = en - st;                 // >= 1 on this path
    int valid = min(max(span, 1), LMAXV);

    // Clamp invalid l to the last valid row: duplicate loads hit L1, keeps
    // the whole body branch-free and maximizes load-level parallelism.
    const float4* crow[LMAXV];
    #pragma unroll
    for (int l = 0; l < LMAXV; l++) {
        int pos = min(st + min(l, valid - 1), SS - 1);
        crow[l] = (const float4*)(ernie + ((size_t)b * SS + pos) * DD);
    }

    // scores: interleave all 4 rows per k-chunk -> 4 independent load streams
    float s0 = 0.f, s1 = 0.f, s2 = 0.f, s3 = 0.f;
    #pragma unroll
    for (int k = 0; k < VPT; k++) {
        float4 c0 = crow[0][k * 32 + lane];
        float4 c1 = crow[1][k * 32 + lane];
        float4 c2 = crow[2][k * 32 + lane];
        float4 c3 = crow[3][k * 32 + lane];
        float4 wk = we[k];
        s0 += wk.x * c0.x + wk.y * c0.y + wk.z * c0.z + wk.w * c0.w;
        s1 += wk.x * c1.x + wk.y * c1.y + wk.z * c1.z + wk.w * c1.w;
        s2 += wk.x * c2.x + wk.y * c2.y + wk.z * c2.z + wk.w * c2.w;
        s3 += wk.x * c3.x + wk.y * c3.y + wk.z * c3.z + wk.w * c3.w;
    }
    #pragma unroll
    for (int o = 16; o; o >>= 1) {
        s0 += __shfl_xor_sync(0xffffffffu, s0, o);
        s1 += __shfl_xor_sync(0xffffffffu, s1, o);
        s2 += __shfl_xor_sync(0xffffffffu, s2, o);
        s3 += __shfl_xor_sync(0xffffffffu, s3, o);
    }

    // masked softmax over l < valid
    float sc[LMAXV] = {s0, s1, s2, s3};
    float m = sc[0];
    #pragma unroll
    for (int l = 1; l < LMAXV; l++) if (l < valid) m = fmaxf(m, sc[l]);
    float a[LMAXV];
    float sum = 0.f;
    #pragma unroll
    for (int l = 0; l < LMAXV; l++) {
        a[l] = (l < valid) ? __expf(sc[l] - m) : 0.f;
        sum += a[l];
    }
    float inv = 1.f / sum;

    // pooled: reload chars (L1 hits), compute and store per k-chunk
    float a0 = a[0] * inv, a1 = a[1] * inv, a2 = a[2] * inv, a3 = a[3] * inv;
    #pragma unroll
    for (int k = 0; k < VPT; k++) {
        float4 c0 = crow[0][k * 32 + lane];
        float4 c1 = crow[1][k * 32 + lane];
        float4 c2 = crow[2][k * 32 + lane];
        float4 c3 = crow[3][k * 32 + lane];
        float4 r;
        r.x = a0 * c0.x + a1 * c1.x + a2 * c2.x + a3 * c3.x;
        r.y = a0 * c0.y + a1 * c1.y + a2 * c2.y + a3 * c3.y;
        r.z = a0 * c0.z + a1 * c1.z + a2 * c2.z + a3 * c3.z;
        r.w = a0 * c0.w + a1 * c1.w + a2 * c2.w + a3 * c3.w;
        __stcs(&orow[k * 32 + lane], r);
    }
}

extern "C" void kernel_launch(void* const* d_in, const int* in_sizes, int n_in,
                              void* d_out, int out_size) {
    const float* ernie = (const float*)d_in[0];
    const float* emb   = (const float*)d_in[1];
    const int*   widx  = (const int*)d_in[2];
    float*       out   = (float*)d_out;

    find_first_kernel<<<BB, 32>>>(widx);
    int total = BB * WW;                      // 19200 warps
    weighted_embed_kernel<<<(total + 7) / 8, 256>>>(ernie, emb, widx, out);
}

// round 4
// speedup vs baseline: 1.4505x; 1.4505x over previous
#include <cuda_runtime.h>

// Problem constants (fixed shapes from reference_code)
#define BB    64
#define WW    300
#define SS    512
#define DD    768
#define LMAXV 4
#define VPT   6          // float4 chunks per lane: (768/4)/32

__device__ int g_first[BB];
__device__ int g_fill[BB];

// Pass 1: per-batch first break index and fill word id
__global__ void find_first_kernel(const int* __restrict__ word_index) {
    int b = blockIdx.x;
    int lane = threadIdx.x & 31;
    int warp = threadIdx.x >> 5;
    __shared__ int wmin[4];
    int best = WW;
    for (int w = threadIdx.x; w < WW; w += blockDim.x) {
        const int* wi = word_index + (b * WW + w) * 3;
        int st = wi[1], en = wi[2];
        if (en < SS && (en - st) <= 0) best = min(best, w);
    }
    #pragma unroll
    for (int o = 16; o; o >>= 1) best = min(best, __shfl_xor_sync(0xffffffffu, best, o));
    if (lane == 0) wmin[warp] = best;
    __syncthreads();
    if (threadIdx.x == 0) {
        best = min(min(wmin[0], wmin[1]), min(wmin[2], wmin[3]));
        g_first[b] = best;
        int fw = min(best, WW - 1);
        g_fill[b] = word_index[(b * WW + fw) * 3];
    }
}

// Pass 2: one warp per (b,w). Loads identical to R2 (only valid rows, no
// cache hints); all shuffle reductions deferred to maximize per-warp MLP.
__global__ __launch_bounds__(256) void weighted_embed_kernel(
    const float* __restrict__ ernie,
    const float* __restrict__ emb,
    const int*   __restrict__ word_index,
    float*       __restrict__ out)
{
    int gw = blockIdx.x * 8 + (threadIdx.x >> 5);
    if (gw >= BB * WW) return;
    int lane = threadIdx.x & 31;
    int b = gw / WW, w = gw - b * WW;

    float4* orow = (float4*)(out + (size_t)gw * DD);

    // Fill path: w >= first  ->  out = word_embedding[fill_id]
    if (w >= g_first[b]) {
        const float4* frow = (const float4*)(emb + (size_t)g_fill[b] * DD);
        #pragma unroll
        for (int k = 0; k < VPT; k++) orow[k * 32 + lane] = frow[k * 32 + lane];
        return;
    }

    const int* wi = word_index + gw * 3;
    int wid = wi[0], st = wi[1], en = wi[2];

    // we = word_embedding[wid], kept in registers
    const float4* werow = (const float4*)(emb + (size_t)wid * DD);
    float4 we[VPT];
    #pragma unroll
    for (int k = 0; k < VPT; k++) we[k] = werow[k * 32 + lane];

    // Out-of-range path: out = we
    if (en >= SS) {
        #pragma unroll
        for (int k = 0; k < VPT; k++) orow[k * 32 + lane] = we[k];
        return;
    }

    int span  = en - st;                  // >= 1 on this path
    int valid = min(max(span, 1), LMAXV);

    const float* eb = ernie + (size_t)b * SS * DD;
    const float4* crow[LMAXV];
    #pragma unroll
    for (int l = 0; l < LMAXV; l++)
        crow[l] = (const float4*)(eb + (size_t)min(st + l, SS - 1) * DD);

    // Per-lane partial dots for all valid rows BEFORE any shuffle:
    // up to 24 independent LDG.128 in flight per warp.
    float s[LMAXV] = {0.f, 0.f, 0.f, 0.f};
    #pragma unroll
    for (int l = 0; l < LMAXV; l++) {
        if (l < valid) {
            #pragma unroll
            for (int k = 0; k < VPT; k++) {
                float4 c = crow[l][k * 32 + lane];
                float4 wk = we[k];
                s[l] += wk.x * c.x + wk.y * c.y + wk.z * c.z + wk.w * c.w;
            }
        }
    }
    // Four interleaved butterfly chains (invalid rows reduce zeros).
    #pragma unroll
    for (int o = 16; o; o >>= 1) {
        s[0] += __shfl_xor_sync(0xffffffffu, s[0], o);
        s[1] += __shfl_xor_sync(0xffffffffu, s[1], o);
        s[2] += __shfl_xor_sync(0xffffffffu, s[2], o);
        s[3] += __shfl_xor_sync(0xffffffffu, s[3], o);
    }

    // masked softmax over l < valid
    float m = s[0];
    #pragma unroll
    for (int l = 1; l < LMAXV; l++) if (l < valid) m = fmaxf(m, s[l]);
    float a[LMAXV];
    float sum = 0.f;
    #pragma unroll
    for (int l = 0; l < LMAXV; l++) {
        a[l] = (l < valid) ? __expf(s[l] - m) : 0.f;
        sum += a[l];
    }
    float inv = 1.f / sum;
    #pragma unroll
    for (int l = 0; l < LMAXV; l++) a[l] *= inv;

    // Pooling: reload rows (L1 hits), compute and store per k-chunk.
    #pragma unroll
    for (int k = 0; k < VPT; k++) {
        float4 r = make_float4(0.f, 0.f, 0.f, 0.f);
        #pragma unroll
        for (int l = 0; l < LMAXV; l++) {
            if (l < valid) {
                float4 c = crow[l][k * 32 + lane];
                r.x += a[l] * c.x;
                r.y += a[l] * c.y;
                r.z += a[l] * c.z;
                r.w += a[l] * c.w;
            }
        }
        orow[k * 32 + lane] = r;
    }
}

extern "C" void kernel_launch(void* const* d_in, const int* in_sizes, int n_in,
                              void* d_out, int out_size) {
    const float* ernie = (const float*)d_in[0];
    const float* emb   = (const float*)d_in[1];
    const int*   widx  = (const int*)d_in[2];
    float*       out   = (float*)d_out;

    find_first_kernel<<<BB, 128>>>(widx);
    int total = BB * WW;                      // 19200 warps
    weighted_embed_kernel<<<(total + 7) / 8, 256>>>(ernie, emb, widx, out);
}